// round 1
// baseline (speedup 1.0000x reference)
#include <cuda_runtime.h>
#include <math.h>

#define B_  2
#define T_  2048
#define EMB 1024
#define H_  16
#define D_  64
#define M_  (B_ * T_)          // 4096
#define N1  (3 * H_ * D_)      // 3072
#define N2  EMB                // 1024
#define SCALE 0.125f           // 64^-0.5

// ---------------- scratch (device globals: allocation-free) ----------------
__device__ float g_Q[B_ * H_ * T_ * D_];   // 16 MiB, pre-scaled by SCALE
__device__ float g_K[B_ * H_ * T_ * D_];
__device__ float g_V[B_ * H_ * T_ * D_];
__device__ float g_O[M_ * EMB];            // attention output, [b,t,h*D+d]

// ---------------- GEMM 1: qkv = x @ Wqkv + b, scatter into Q/K/V -----------
// Tiles: BM=128, BN=128, BK=16, 256 threads, 8x8 per-thread microtile.
__global__ __launch_bounds__(256) void gemm_qkv(
    const float* __restrict__ X,      // [4096, 1024]
    const float* __restrict__ W,      // [1024, 3072]
    const float* __restrict__ bias)   // [3072]
{
    __shared__ float As[16][128];
    __shared__ float Bs[16][128];

    const int bm = blockIdx.y * 128;
    const int bn = blockIdx.x * 128;
    const int tid = threadIdx.x;

    const int arow = tid >> 2;          // 0..63
    const int acol = (tid & 3) * 4;     // 0,4,8,12
    const int brow = tid >> 5;          // 0..7
    const int bcol = (tid & 31) * 4;    // 0..124

    const int ty = (tid >> 4) * 8;
    const int tx = (tid & 15) * 8;

    float acc[8][8];
#pragma unroll
    for (int i = 0; i < 8; i++)
#pragma unroll
        for (int j = 0; j < 8; j++) acc[i][j] = 0.f;

    for (int k0 = 0; k0 < 1024; k0 += 16) {
#pragma unroll
        for (int h = 0; h < 2; h++) {
            int r = arow + h * 64;
            float4 v = *(const float4*)&X[(size_t)(bm + r) * 1024 + k0 + acol];
            As[acol + 0][r] = v.x; As[acol + 1][r] = v.y;
            As[acol + 2][r] = v.z; As[acol + 3][r] = v.w;
        }
#pragma unroll
        for (int h = 0; h < 2; h++) {
            int r = brow + h * 8;
            *(float4*)&Bs[r][bcol] =
                *(const float4*)&W[(size_t)(k0 + r) * N1 + bn + bcol];
        }
        __syncthreads();

#pragma unroll
        for (int kk = 0; kk < 16; kk++) {
            float a[8], b[8];
#pragma unroll
            for (int i = 0; i < 8; i++) a[i] = As[kk][ty + i];
#pragma unroll
            for (int j = 0; j < 8; j++) b[j] = Bs[kk][tx + j];
#pragma unroll
            for (int i = 0; i < 8; i++)
#pragma unroll
                for (int j = 0; j < 8; j++)
                    acc[i][j] = fmaf(a[i], b[j], acc[i][j]);
        }
        __syncthreads();
    }

    // Epilogue: add bias, route to Q (scaled), K, V in [B,H,T,D]
#pragma unroll
    for (int i = 0; i < 8; i++) {
        int m = bm + ty + i;
        int bb = m >> 11;            // / T_
        int t  = m & (T_ - 1);
#pragma unroll
        for (int j = 0; j < 8; j++) {
            int n = bn + tx + j;
            float val = acc[i][j] + bias[n];
            int sec = n >> 10;
            int rem = n & 1023;
            int h = rem >> 6;
            int d = rem & 63;
            size_t idx = ((size_t)(bb * H_ + h) * T_ + t) * D_ + d;
            if (sec == 0)       g_Q[idx] = val * SCALE;
            else if (sec == 1)  g_K[idx] = val;
            else                g_V[idx] = val;
        }
    }
}

// ---------------- Attention: causal flash-style, fp32 ----------------------
// Grid: (T/128, B*H). 128 threads, one query row per thread.
// q (64f) and o (64f) live in registers; 64-key K/V tiles in smem.
__global__ __launch_bounds__(128) void attn_kernel()
{
    __shared__ float Ks[64 * 64];
    __shared__ float Vs[64 * 64];

    const int qt  = blockIdx.x;
    const int bh  = blockIdx.y;
    const int tid = threadIdx.x;
    const int row = qt * 128 + tid;

    const float* __restrict__ Qb = g_Q + (size_t)bh * T_ * D_;
    const float* __restrict__ Kb = g_K + (size_t)bh * T_ * D_;
    const float* __restrict__ Vb = g_V + (size_t)bh * T_ * D_;

    float4 q4[16];
    const float4* qrow = (const float4*)(Qb + (size_t)row * D_);
#pragma unroll
    for (int i = 0; i < 16; i++) q4[i] = qrow[i];

    float4 o4[16];
#pragma unroll
    for (int i = 0; i < 16; i++) o4[i] = make_float4(0.f, 0.f, 0.f, 0.f);

    float mval = -INFINITY;
    float lval = 0.f;

    const int ntiles = 2 * qt + 2;   // 64-key tiles covering [0, qt*128+128)
    for (int kt = 0; kt < ntiles; kt++) {
        const int base = kt * 64;
        // cooperative tile load: 64x64 floats each = 1024 float4
        const float4* Kp = (const float4*)(Kb + (size_t)base * D_);
        const float4* Vp = (const float4*)(Vb + (size_t)base * D_);
        for (int idx = tid; idx < 1024; idx += 128) {
            ((float4*)Ks)[idx] = Kp[idx];
            ((float4*)Vs)[idx] = Vp[idx];
        }
        __syncthreads();

        int jmax = row - base + 1;
        if (jmax > 64) jmax = 64;
        for (int j = 0; j < jmax; j++) {
            const float4* kr = (const float4*)&Ks[j * 64];
            float s = 0.f;
#pragma unroll
            for (int d4 = 0; d4 < 16; d4++) {
                float4 kv = kr[d4];
                s = fmaf(q4[d4].x, kv.x, s);
                s = fmaf(q4[d4].y, kv.y, s);
                s = fmaf(q4[d4].z, kv.z, s);
                s = fmaf(q4[d4].w, kv.w, s);
            }
            float mnew = fmaxf(mval, s);
            float corr = __expf(mval - mnew);
            float p    = __expf(s - mnew);
            lval = lval * corr + p;
            const float4* vr = (const float4*)&Vs[j * 64];
#pragma unroll
            for (int d4 = 0; d4 < 16; d4++) {
                float4 vv = vr[d4];
                o4[d4].x = fmaf(p, vv.x, o4[d4].x * corr);
                o4[d4].y = fmaf(p, vv.y, o4[d4].y * corr);
                o4[d4].z = fmaf(p, vv.z, o4[d4].z * corr);
                o4[d4].w = fmaf(p, vv.w, o4[d4].w * corr);
            }
            mval = mnew;
        }
        __syncthreads();
    }

    const float inv = 1.f / lval;
    const int bb = bh >> 4;
    const int h  = bh & 15;
    float4* orow = (float4*)(g_O + ((size_t)(bb * T_ + row) * H_ + h) * D_);
#pragma unroll
    for (int i = 0; i < 16; i++) {
        float4 v = o4[i];
        v.x *= inv; v.y *= inv; v.z *= inv; v.w *= inv;
        orow[i] = v;
    }
}

// ---------------- GEMM 2: out = g_O @ Wout + bout ---------------------------
__global__ __launch_bounds__(256) void gemm_out(
    const float* __restrict__ W,      // [1024, 1024]
    const float* __restrict__ bias,   // [1024]
    float* __restrict__ C)            // [4096, 1024]
{
    __shared__ float As[16][128];
    __shared__ float Bs[16][128];

    const int bm = blockIdx.y * 128;
    const int bn = blockIdx.x * 128;
    const int tid = threadIdx.x;

    const int arow = tid >> 2;
    const int acol = (tid & 3) * 4;
    const int brow = tid >> 5;
    const int bcol = (tid & 31) * 4;

    const int ty = (tid >> 4) * 8;
    const int tx = (tid & 15) * 8;

    float acc[8][8];
#pragma unroll
    for (int i = 0; i < 8; i++)
#pragma unroll
        for (int j = 0; j < 8; j++) acc[i][j] = 0.f;

    for (int k0 = 0; k0 < 1024; k0 += 16) {
#pragma unroll
        for (int h = 0; h < 2; h++) {
            int r = arow + h * 64;
            float4 v = *(const float4*)&g_O[(size_t)(bm + r) * 1024 + k0 + acol];
            As[acol + 0][r] = v.x; As[acol + 1][r] = v.y;
            As[acol + 2][r] = v.z; As[acol + 3][r] = v.w;
        }
#pragma unroll
        for (int h = 0; h < 2; h++) {
            int r = brow + h * 8;
            *(float4*)&Bs[r][bcol] =
                *(const float4*)&W[(size_t)(k0 + r) * N2 + bn + bcol];
        }
        __syncthreads();

#pragma unroll
        for (int kk = 0; kk < 16; kk++) {
            float a[8], b[8];
#pragma unroll
            for (int i = 0; i < 8; i++) a[i] = As[kk][ty + i];
#pragma unroll
            for (int j = 0; j < 8; j++) b[j] = Bs[kk][tx + j];
#pragma unroll
            for (int i = 0; i < 8; i++)
#pragma unroll
                for (int j = 0; j < 8; j++)
                    acc[i][j] = fmaf(a[i], b[j], acc[i][j]);
        }
        __syncthreads();
    }

#pragma unroll
    for (int i = 0; i < 8; i++) {
        int m = bm + ty + i;
#pragma unroll
        for (int j = 0; j < 8; j += 4) {
            int n = bn + tx + j;
            float4 v;
            v.x = acc[i][j + 0] + bias[n + 0];
            v.y = acc[i][j + 1] + bias[n + 1];
            v.z = acc[i][j + 2] + bias[n + 2];
            v.w = acc[i][j + 3] + bias[n + 3];
            *(float4*)&C[(size_t)m * 1024 + n] = v;
        }
    }
}

// ---------------- launch ----------------------------------------------------
extern "C" void kernel_launch(void* const* d_in, const int* in_sizes, int n_in,
                              void* d_out, int out_size)
{
    const float* x    = (const float*)d_in[0];
    const float* Wqkv = (const float*)d_in[1];
    const float* bqkv = (const float*)d_in[2];
    const float* Wout = (const float*)d_in[3];
    const float* bout = (const float*)d_in[4];
    float* out = (float*)d_out;

    dim3 g1(N1 / 128, M_ / 128);   // (24, 32)
    gemm_qkv<<<g1, 256>>>(x, Wqkv, bqkv);

    dim3 ga(T_ / 128, B_ * H_);    // (16, 32)
    attn_kernel<<<ga, 128>>>();

    dim3 g2(N2 / 128, M_ / 128);   // (8, 32)
    gemm_out<<<g2, 256>>>(Wout, bout, out);
}

// round 3
// speedup vs baseline: 1.7237x; 1.7237x over previous
#include <cuda_runtime.h>
#include <math.h>
#include <stdint.h>

#define B_  2
#define T_  2048
#define EMB 1024
#define H_  16
#define D_  64
#define M_  (B_ * T_)          // 4096
#define N1  3072
#define N2  1024
#define SCALE 0.125f

// ---------------- scratch ----------------
__device__ float g_Q[B_ * H_ * T_ * D_];   // pre-scaled by SCALE
__device__ float g_K[B_ * H_ * T_ * D_];
__device__ float g_V[B_ * H_ * T_ * D_];
__device__ float g_O[M_ * EMB];

// ---------------- tf32 helpers ----------------
__device__ __forceinline__ uint32_t f2tf(float x) {
    uint32_t r;
    asm("cvt.rna.tf32.f32 %0, %1;" : "=r"(r) : "f"(x));
    return r;
}
__device__ __forceinline__ void split1(float v, uint32_t& hi, uint32_t& lo) {
    hi = f2tf(v);
    lo = f2tf(v - __uint_as_float(hi));
}
__device__ __forceinline__ void split4(float4 v, uint4& hi, uint4& lo) {
    split1(v.x, hi.x, lo.x); split1(v.y, hi.y, lo.y);
    split1(v.z, hi.z, lo.z); split1(v.w, hi.w, lo.w);
}
__device__ __forceinline__ void mma8(float* c, const uint32_t* a, const uint32_t* b) {
    asm volatile(
        "mma.sync.aligned.m16n8k8.row.col.f32.tf32.tf32.f32 "
        "{%0,%1,%2,%3},{%4,%5,%6,%7},{%8,%9},{%0,%1,%2,%3};\n"
        : "+f"(c[0]), "+f"(c[1]), "+f"(c[2]), "+f"(c[3])
        : "r"(a[0]), "r"(a[1]), "r"(a[2]), "r"(a[3]), "r"(b[0]), "r"(b[1]));
}

// ================= GEMM (3xTF32): C = A[Mx1024] @ W[1024xN] + bias =========
// Block 128x128, 8 warps (2x4), warp tile 64x32, BK=16.
// MODE 0: scatter qkv -> g_Q (scaled), g_K, g_V.  MODE 1: A := g_O, write C.
#define AS_STR 20
#define BS_STR 136

template<int N, int MODE>
__global__ __launch_bounds__(256, 1) void gemm3_tf32(
    const float* __restrict__ Ain, const float* __restrict__ W,
    const float* __restrict__ bias, float* __restrict__ C)
{
    __shared__ uint32_t As_hi[128 * AS_STR], As_lo[128 * AS_STR];
    __shared__ uint32_t Bs_hi[16 * BS_STR],  Bs_lo[16 * BS_STR];

    const float* __restrict__ A = (MODE == 0) ? Ain : (const float*)g_O;

    const int tid  = threadIdx.x;
    const int warp = tid >> 5, lane = tid & 31;
    const int g    = lane >> 2, tg = lane & 3;
    const int wy   = warp >> 2, wx = warp & 3;      // 2 x 4 warps
    const int bm   = blockIdx.y * 128, bn = blockIdx.x * 128;

    float acc[4][4][4];
#pragma unroll
    for (int i = 0; i < 4; i++)
#pragma unroll
        for (int j = 0; j < 4; j++)
#pragma unroll
            for (int r = 0; r < 4; r++) acc[i][j][r] = 0.f;

    const int am = tid >> 2;           // 0..63
    const int ak = (tid & 3) * 4;      // 0,4,8,12
    const int br = tid >> 5;           // reuse warp idx? no: B loads below use idx math

    float4 pa[2], pb[2];
    pa[0] = *(const float4*)&A[(size_t)(bm + am) * 1024 + ak];
    pa[1] = *(const float4*)&A[(size_t)(bm + am + 64) * 1024 + ak];
#pragma unroll
    for (int i = 0; i < 2; i++) {
        int idx = tid + i * 256;
        pb[i] = *(const float4*)&W[(size_t)(idx >> 5) * N + bn + (idx & 31) * 4];
    }
    (void)br;

    for (int kb = 0; kb < 64; kb++) {
        uint4 h, l;
        split4(pa[0], h, l);
        *(uint4*)&As_hi[am * AS_STR + ak] = h;  *(uint4*)&As_lo[am * AS_STR + ak] = l;
        split4(pa[1], h, l);
        *(uint4*)&As_hi[(am + 64) * AS_STR + ak] = h;  *(uint4*)&As_lo[(am + 64) * AS_STR + ak] = l;
#pragma unroll
        for (int i = 0; i < 2; i++) {
            int idx = tid + i * 256;
            split4(pb[i], h, l);
            *(uint4*)&Bs_hi[(idx >> 5) * BS_STR + (idx & 31) * 4] = h;
            *(uint4*)&Bs_lo[(idx >> 5) * BS_STR + (idx & 31) * 4] = l;
        }
        __syncthreads();

        if (kb < 63) {
            int k0 = (kb + 1) * 16;
            pa[0] = *(const float4*)&A[(size_t)(bm + am) * 1024 + k0 + ak];
            pa[1] = *(const float4*)&A[(size_t)(bm + am + 64) * 1024 + k0 + ak];
#pragma unroll
            for (int i = 0; i < 2; i++) {
                int idx = tid + i * 256;
                pb[i] = *(const float4*)&W[(size_t)(k0 + (idx >> 5)) * N + bn + (idx & 31) * 4];
            }
        }

#pragma unroll
        for (int ka = 0; ka < 2; ka++) {
            uint32_t afh[4][4], afl[4][4], bfh[4][2], bfl[4][2];
#pragma unroll
            for (int ma = 0; ma < 4; ma++) {
                int r = wy * 64 + ma * 16 + g;
                int c0 = ka * 8 + tg;
                afh[ma][0] = As_hi[r * AS_STR + c0];
                afh[ma][1] = As_hi[(r + 8) * AS_STR + c0];
                afh[ma][2] = As_hi[r * AS_STR + c0 + 4];
                afh[ma][3] = As_hi[(r + 8) * AS_STR + c0 + 4];
                afl[ma][0] = As_lo[r * AS_STR + c0];
                afl[ma][1] = As_lo[(r + 8) * AS_STR + c0];
                afl[ma][2] = As_lo[r * AS_STR + c0 + 4];
                afl[ma][3] = As_lo[(r + 8) * AS_STR + c0 + 4];
            }
#pragma unroll
            for (int na = 0; na < 4; na++) {
                int cN = wx * 32 + na * 8 + g;
                bfh[na][0] = Bs_hi[(ka * 8 + tg) * BS_STR + cN];
                bfh[na][1] = Bs_hi[(ka * 8 + tg + 4) * BS_STR + cN];
                bfl[na][0] = Bs_lo[(ka * 8 + tg) * BS_STR + cN];
                bfl[na][1] = Bs_lo[(ka * 8 + tg + 4) * BS_STR + cN];
            }
#pragma unroll
            for (int ma = 0; ma < 4; ma++)
#pragma unroll
                for (int na = 0; na < 4; na++) {
                    mma8(acc[ma][na], afh[ma], bfh[na]);
                    mma8(acc[ma][na], afl[ma], bfh[na]);
                    mma8(acc[ma][na], afh[ma], bfl[na]);
                }
        }
        __syncthreads();
    }

    // ---------- epilogue ----------
#pragma unroll
    for (int ma = 0; ma < 4; ma++) {
        int m0 = bm + wy * 64 + ma * 16 + g;
#pragma unroll
        for (int na = 0; na < 4; na++) {
            int n = bn + wx * 32 + na * 8 + tg * 2;
            float b0v = bias[n], b1v = bias[n + 1];
#pragma unroll
            for (int half = 0; half < 2; half++) {
                int m = m0 + half * 8;
                float2 v;
                v.x = acc[ma][na][half * 2 + 0] + b0v;
                v.y = acc[ma][na][half * 2 + 1] + b1v;
                if (MODE == 0) {
                    int bb  = m >> 11, t = m & (T_ - 1);
                    int sec = n >> 10, rem = n & 1023;
                    int h = rem >> 6, d = rem & 63;
                    size_t idx = ((size_t)(bb * H_ + h) * T_ + t) * D_ + d;
                    if (sec == 0) { v.x *= SCALE; v.y *= SCALE; *(float2*)&g_Q[idx] = v; }
                    else if (sec == 1) { *(float2*)&g_K[idx] = v; }
                    else               { *(float2*)&g_V[idx] = v; }
                } else {
                    *(float2*)&C[(size_t)m * N2 + n] = v;
                }
            }
        }
    }
}

// ================= Attention (3xTF32 flash) ================================
// Block: 256 threads = 8 warps, Br=128 (16 rows/warp), Bc=64.
#define KS_STR 68
#define VS_STR 72
#define PS_STR 68
#define ATTN_WORDS (2*64*KS_STR + 2*64*VS_STR + 2*128*PS_STR)
#define ATTN_SMEM  (ATTN_WORDS * 4)

__global__ __launch_bounds__(256, 1) void attn3_tf32()
{
    extern __shared__ uint32_t sm[];
    uint32_t* Ks_hi = sm;
    uint32_t* Ks_lo = Ks_hi + 64 * KS_STR;
    uint32_t* Vs_hi = Ks_lo + 64 * KS_STR;
    uint32_t* Vs_lo = Vs_hi + 64 * VS_STR;
    uint32_t* Ps_hi = Vs_lo + 64 * VS_STR;
    uint32_t* Ps_lo = Ps_hi + 128 * PS_STR;

    const int tid = threadIdx.x, warp = tid >> 5, lane = tid & 31;
    const int g = lane >> 2, tg = lane & 3;
    const int qb = blockIdx.x, bh = blockIdx.y;
    const int wrow = warp * 16;                 // local row base
    const int qr0  = qb * 128 + wrow;           // global row base for this warp

    const float* __restrict__ Qg = g_Q + (size_t)bh * T_ * D_;
    const float* __restrict__ Kg = g_K + (size_t)bh * T_ * D_;
    const float* __restrict__ Vg = g_V + (size_t)bh * T_ * D_;

    // Q fragments hi/lo, loaded straight from global
    uint32_t qfh[8][4], qfl[8][4];
#pragma unroll
    for (int ka = 0; ka < 8; ka++) {
        int c = ka * 8 + tg;
        float q0 = Qg[(size_t)(qr0 + g) * D_ + c];
        float q1 = Qg[(size_t)(qr0 + g + 8) * D_ + c];
        float q2 = Qg[(size_t)(qr0 + g) * D_ + c + 4];
        float q3 = Qg[(size_t)(qr0 + g + 8) * D_ + c + 4];
        split1(q0, qfh[ka][0], qfl[ka][0]);
        split1(q1, qfh[ka][1], qfl[ka][1]);
        split1(q2, qfh[ka][2], qfl[ka][2]);
        split1(q3, qfh[ka][3], qfl[ka][3]);
    }

    float of[8][4];
#pragma unroll
    for (int j = 0; j < 8; j++)
#pragma unroll
        for (int r = 0; r < 4; r++) of[j][r] = 0.f;

    const float NEG_INF = __int_as_float(0xff800000);
    float mrow[2] = {NEG_INF, NEG_INF};
    float lrow[2] = {0.f, 0.f};

    const int ntiles = 2 * qb + 2;
    for (int kt = 0; kt < ntiles; kt++) {
        const int base = kt * 64;
        __syncthreads();   // previous-tile consumers done with Ks/Vs
        for (int i = tid; i < 1024; i += 256) {
            int r = i >> 4, d4 = (i & 15) * 4;
            uint4 h, l;
            split4(*(const float4*)&Kg[(size_t)(base + r) * D_ + d4], h, l);
            *(uint4*)&Ks_hi[r * KS_STR + d4] = h;
            *(uint4*)&Ks_lo[r * KS_STR + d4] = l;
            split4(*(const float4*)&Vg[(size_t)(base + r) * D_ + d4], h, l);
            *(uint4*)&Vs_hi[r * VS_STR + d4] = h;
            *(uint4*)&Vs_lo[r * VS_STR + d4] = l;
        }
        __syncthreads();

        if (base > qr0 + 15) continue;   // tile fully above diagonal for this warp

        // ---- S = Q K^T (3xTF32) ----
        float sacc[8][4];
#pragma unroll
        for (int j = 0; j < 8; j++)
#pragma unroll
            for (int r = 0; r < 4; r++) sacc[j][r] = 0.f;

#pragma unroll
        for (int ka = 0; ka < 8; ka++) {
            int c = ka * 8 + tg;
#pragma unroll
            for (int na = 0; na < 8; na++) {
                int row = (na * 8 + g) * KS_STR;
                uint32_t bh2[2], bl2[2];
                bh2[0] = Ks_hi[row + c];     bh2[1] = Ks_hi[row + c + 4];
                bl2[0] = Ks_lo[row + c];     bl2[1] = Ks_lo[row + c + 4];
                mma8(sacc[na], qfh[ka], bh2);
                mma8(sacc[na], qfl[ka], bh2);
                mma8(sacc[na], qfh[ka], bl2);
            }
        }

        // ---- causal mask ----
        if (base + 63 > qr0) {
#pragma unroll
            for (int na = 0; na < 8; na++)
#pragma unroll
                for (int r = 0; r < 4; r++) {
                    int q = qr0 + g + (r >> 1) * 8;
                    int j = base + na * 8 + tg * 2 + (r & 1);
                    if (j > q) sacc[na][r] = NEG_INF;
                }
        }

        // ---- online softmax ----
#pragma unroll
        for (int h = 0; h < 2; h++) {
            float rm = NEG_INF;
#pragma unroll
            for (int na = 0; na < 8; na++) {
                rm = fmaxf(rm, sacc[na][h * 2 + 0]);
                rm = fmaxf(rm, sacc[na][h * 2 + 1]);
            }
            rm = fmaxf(rm, __shfl_xor_sync(0xffffffffu, rm, 1));
            rm = fmaxf(rm, __shfl_xor_sync(0xffffffffu, rm, 2));
            float mn   = fmaxf(mrow[h], rm);
            float corr = __expf(mrow[h] - mn);
            mrow[h] = mn;
            float sum = 0.f;
#pragma unroll
            for (int na = 0; na < 8; na++) {
                float p0 = __expf(sacc[na][h * 2 + 0] - mn);
                float p1 = __expf(sacc[na][h * 2 + 1] - mn);
                sacc[na][h * 2 + 0] = p0;
                sacc[na][h * 2 + 1] = p1;
                sum += p0 + p1;
            }
            sum += __shfl_xor_sync(0xffffffffu, sum, 1);
            sum += __shfl_xor_sync(0xffffffffu, sum, 2);
            lrow[h] = lrow[h] * corr + sum;
#pragma unroll
            for (int na = 0; na < 8; na++) {
                of[na][h * 2 + 0] *= corr;
                of[na][h * 2 + 1] *= corr;
            }
        }

        // ---- store P hi/lo (per-warp private rows) ----
#pragma unroll
        for (int na = 0; na < 8; na++) {
            int q = wrow + g;
            int j = na * 8 + tg * 2;
            uint2 h0, l0, h1, l1;
            split1(sacc[na][0], h0.x, l0.x); split1(sacc[na][1], h0.y, l0.y);
            split1(sacc[na][2], h1.x, l1.x); split1(sacc[na][3], h1.y, l1.y);
            *(uint2*)&Ps_hi[q * PS_STR + j]       = h0;
            *(uint2*)&Ps_lo[q * PS_STR + j]       = l0;
            *(uint2*)&Ps_hi[(q + 8) * PS_STR + j] = h1;
            *(uint2*)&Ps_lo[(q + 8) * PS_STR + j] = l1;
        }
        __syncwarp();

        // ---- O += P V (3xTF32) ----
#pragma unroll
        for (int ka = 0; ka < 8; ka++) {
            int c = ka * 8 + tg;
            uint32_t pah[4], pal[4];
            int r = wrow + g;
            pah[0] = Ps_hi[r * PS_STR + c];       pal[0] = Ps_lo[r * PS_STR + c];
            pah[1] = Ps_hi[(r + 8) * PS_STR + c]; pal[1] = Ps_lo[(r + 8) * PS_STR + c];
            pah[2] = Ps_hi[r * PS_STR + c + 4];   pal[2] = Ps_lo[r * PS_STR + c + 4];
            pah[3] = Ps_hi[(r + 8) * PS_STR + c + 4]; pal[3] = Ps_lo[(r + 8) * PS_STR + c + 4];
#pragma unroll
            for (int na = 0; na < 8; na++) {
                int nn = na * 8 + g;
                uint32_t vh2[2], vl2[2];
                vh2[0] = Vs_hi[(ka * 8 + tg) * VS_STR + nn];
                vh2[1] = Vs_hi[(ka * 8 + tg + 4) * VS_STR + nn];
                vl2[0] = Vs_lo[(ka * 8 + tg) * VS_STR + nn];
                vl2[1] = Vs_lo[(ka * 8 + tg + 4) * VS_STR + nn];
                mma8(of[na], pah, vh2);
                mma8(of[na], pal, vh2);
                mma8(of[na], pah, vl2);
            }
        }
    }

    // ---- finalize ----
    const int bb = bh >> 4, hh = bh & 15;
    float inv0 = 1.f / lrow[0];
    float inv1 = 1.f / lrow[1];
    int q = qb * 128 + wrow + g;
    float* o0 = g_O + ((size_t)(bb * T_ + q)) * EMB + hh * D_;
    float* o8 = g_O + ((size_t)(bb * T_ + q + 8)) * EMB + hh * D_;
#pragma unroll
    for (int na = 0; na < 8; na++) {
        int d = na * 8 + tg * 2;
        float2 v0, v1;
        v0.x = of[na][0] * inv0; v0.y = of[na][1] * inv0;
        v1.x = of[na][2] * inv1; v1.y = of[na][3] * inv1;
        *(float2*)&o0[d] = v0;
        *(float2*)&o8[d] = v1;
    }
}

// ---------------- launch ----------------
extern "C" void kernel_launch(void* const* d_in, const int* in_sizes, int n_in,
                              void* d_out, int out_size)
{
    const float* x    = (const float*)d_in[0];
    const float* Wqkv = (const float*)d_in[1];
    const float* bqkv = (const float*)d_in[2];
    const float* Wout = (const float*)d_in[3];
    const float* bout = (const float*)d_in[4];
    float* out = (float*)d_out;

    static bool attr_done = false;
    if (!attr_done) {
        cudaFuncSetAttribute(attn3_tf32, cudaFuncAttributeMaxDynamicSharedMemorySize, ATTN_SMEM);
        attr_done = true;
    }

    dim3 g1(N1 / 128, M_ / 128);   // (24, 32)
    gemm3_tf32<N1, 0><<<g1, 256>>>(x, Wqkv, bqkv, nullptr);

    dim3 ga(T_ / 128, B_ * H_);    // (16, 32)
    attn3_tf32<<<ga, 256, ATTN_SMEM>>>();

    dim3 g2(N2 / 128, M_ / 128);   // (8, 32)
    gemm3_tf32<N2, 1><<<g2, 256>>>(nullptr, Wout, bout, out);
}

// round 4
// speedup vs baseline: 3.2476x; 1.8841x over previous
#include <cuda_runtime.h>
#include <cuda_bf16.h>
#include <math.h>
#include <stdint.h>

#define B_  2
#define T_  2048
#define EMB 1024
#define H_  16
#define D_  64
#define M_  (B_ * T_)          // 4096
#define N1  3072
#define N2  1024
#define SCALE 0.125f

// ---------------- scratch ----------------
__device__ float g_Q[B_ * H_ * T_ * D_];   // pre-scaled by SCALE
__device__ float g_K[B_ * H_ * T_ * D_];
__device__ float g_V[B_ * H_ * T_ * D_];
__device__ float g_O[M_ * EMB];

// ---------------- bf16 split helpers ----------------
// pack2(x,y): x -> low half (even k), y -> high half (odd k)
__device__ __forceinline__ uint32_t pack2(float x, float y) {
    uint32_t r;
    asm("cvt.rn.bf16x2.f32 %0, %1, %2;" : "=r"(r) : "f"(y), "f"(x));
    return r;
}
__device__ __forceinline__ void split2(float x, float y, uint32_t& hi, uint32_t& lo) {
    hi = pack2(x, y);
    __nv_bfloat162 h = *reinterpret_cast<__nv_bfloat162*>(&hi);
    lo = pack2(x - __bfloat162float(h.x), y - __bfloat162float(h.y));
}

// m16n8k16 bf16 mma, fp32 accumulate (acc layout identical to m16n8k8)
__device__ __forceinline__ void mma16(float* c, const uint32_t* a, const uint32_t* b) {
    asm volatile(
        "mma.sync.aligned.m16n8k16.row.col.f32.bf16.bf16.f32 "
        "{%0,%1,%2,%3},{%4,%5,%6,%7},{%8,%9},{%0,%1,%2,%3};\n"
        : "+f"(c[0]), "+f"(c[1]), "+f"(c[2]), "+f"(c[3])
        : "r"(a[0]), "r"(a[1]), "r"(a[2]), "r"(a[3]), "r"(b[0]), "r"(b[1]));
}

// ================= GEMM (3xBF16): C = A[Mx1024] @ W[1024xN] + bias =========
// Block 128x128, 8 warps (2x4), warp tile 64x32, BK=32 (2 k16 chunks).
// Smem holds k-PAIRS packed as bf16x2 in u32.
// MODE 0: scatter qkv -> g_Q (scaled), g_K, g_V.  MODE 1: A := g_O, write C.
#define AS_STR 20    // u32 per A row (16 kpairs + pad)
#define BS_STR 136   // u32 per B kpair-row (128 n + pad)

template<int N, int MODE>
__global__ __launch_bounds__(256, 1) void gemmb(
    const float* __restrict__ Ain, const float* __restrict__ W,
    const float* __restrict__ bias, float* __restrict__ C)
{
    __shared__ uint32_t As_hi[128 * AS_STR], As_lo[128 * AS_STR];
    __shared__ uint32_t Bs_hi[16 * BS_STR],  Bs_lo[16 * BS_STR];

    const float* __restrict__ A = (MODE == 0) ? Ain : (const float*)g_O;

    const int tid  = threadIdx.x;
    const int warp = tid >> 5, lane = tid & 31;
    const int g    = lane >> 2, tg = lane & 3;
    const int wy   = warp >> 2, wx = warp & 3;      // 2 x 4 warps
    const int bm   = blockIdx.y * 128, bn = blockIdx.x * 128;

    float acc[4][4][4];
#pragma unroll
    for (int i = 0; i < 4; i++)
#pragma unroll
        for (int j = 0; j < 4; j++)
#pragma unroll
            for (int r = 0; r < 4; r++) acc[i][j][r] = 0.f;

    // A tile: 128 rows x 32 k = 1024 float4; 4 per thread.
    // B tile: 32 k x 128 n; loaded as 512 row-PAIR float4 ops; 2 per thread.
    float4 pa[4], pb0[2], pb1[2];
#pragma unroll
    for (int i = 0; i < 4; i++) {
        int idx = tid + i * 256, row = idx >> 3, c4 = idx & 7;
        pa[i] = *(const float4*)&A[(size_t)(bm + row) * 1024 + 4 * c4];
    }
#pragma unroll
    for (int i = 0; i < 2; i++) {
        int idx = tid + i * 256, kp = idx >> 5, c4 = idx & 31;
        pb0[i] = *(const float4*)&W[(size_t)(2 * kp)     * N + bn + 4 * c4];
        pb1[i] = *(const float4*)&W[(size_t)(2 * kp + 1) * N + bn + 4 * c4];
    }

    for (int kb = 0; kb < 32; kb++) {
#pragma unroll
        for (int i = 0; i < 4; i++) {
            int idx = tid + i * 256, row = idx >> 3, c4 = idx & 7;
            uint2 h, l;
            split2(pa[i].x, pa[i].y, h.x, l.x);
            split2(pa[i].z, pa[i].w, h.y, l.y);
            *(uint2*)&As_hi[row * AS_STR + 2 * c4] = h;
            *(uint2*)&As_lo[row * AS_STR + 2 * c4] = l;
        }
#pragma unroll
        for (int i = 0; i < 2; i++) {
            int idx = tid + i * 256, kp = idx >> 5, c4 = idx & 31;
            uint4 h, l;
            split2(pb0[i].x, pb1[i].x, h.x, l.x);
            split2(pb0[i].y, pb1[i].y, h.y, l.y);
            split2(pb0[i].z, pb1[i].z, h.z, l.z);
            split2(pb0[i].w, pb1[i].w, h.w, l.w);
            *(uint4*)&Bs_hi[kp * BS_STR + 4 * c4] = h;
            *(uint4*)&Bs_lo[kp * BS_STR + 4 * c4] = l;
        }
        __syncthreads();

        if (kb < 31) {
            int k0 = (kb + 1) * 32;
#pragma unroll
            for (int i = 0; i < 4; i++) {
                int idx = tid + i * 256, row = idx >> 3, c4 = idx & 7;
                pa[i] = *(const float4*)&A[(size_t)(bm + row) * 1024 + k0 + 4 * c4];
            }
#pragma unroll
            for (int i = 0; i < 2; i++) {
                int idx = tid + i * 256, kp = idx >> 5, c4 = idx & 31;
                pb0[i] = *(const float4*)&W[(size_t)(k0 + 2 * kp)     * N + bn + 4 * c4];
                pb1[i] = *(const float4*)&W[(size_t)(k0 + 2 * kp + 1) * N + bn + 4 * c4];
            }
        }

#pragma unroll
        for (int ka = 0; ka < 2; ka++) {
            uint32_t afh[4][4], afl[4][4], bfh[4][2], bfl[4][2];
#pragma unroll
            for (int ma = 0; ma < 4; ma++) {
                int r = wy * 64 + ma * 16 + g;
                int c0 = ka * 8 + tg;
                afh[ma][0] = As_hi[r * AS_STR + c0];
                afh[ma][1] = As_hi[(r + 8) * AS_STR + c0];
                afh[ma][2] = As_hi[r * AS_STR + c0 + 4];
                afh[ma][3] = As_hi[(r + 8) * AS_STR + c0 + 4];
                afl[ma][0] = As_lo[r * AS_STR + c0];
                afl[ma][1] = As_lo[(r + 8) * AS_STR + c0];
                afl[ma][2] = As_lo[r * AS_STR + c0 + 4];
                afl[ma][3] = As_lo[(r + 8) * AS_STR + c0 + 4];
            }
#pragma unroll
            for (int na = 0; na < 4; na++) {
                int cN = wx * 32 + na * 8 + g;
                bfh[na][0] = Bs_hi[(ka * 8 + tg) * BS_STR + cN];
                bfh[na][1] = Bs_hi[(ka * 8 + tg + 4) * BS_STR + cN];
                bfl[na][0] = Bs_lo[(ka * 8 + tg) * BS_STR + cN];
                bfl[na][1] = Bs_lo[(ka * 8 + tg + 4) * BS_STR + cN];
            }
#pragma unroll
            for (int ma = 0; ma < 4; ma++)
#pragma unroll
                for (int na = 0; na < 4; na++) {
                    mma16(acc[ma][na], afh[ma], bfh[na]);
                    mma16(acc[ma][na], afl[ma], bfh[na]);
                    mma16(acc[ma][na], afh[ma], bfl[na]);
                }
        }
        __syncthreads();
    }

    // ---------- epilogue ----------
#pragma unroll
    for (int ma = 0; ma < 4; ma++) {
        int m0 = bm + wy * 64 + ma * 16 + g;
#pragma unroll
        for (int na = 0; na < 4; na++) {
            int n = bn + wx * 32 + na * 8 + tg * 2;
            float b0v = bias[n], b1v = bias[n + 1];
#pragma unroll
            for (int half = 0; half < 2; half++) {
                int m = m0 + half * 8;
                float2 v;
                v.x = acc[ma][na][half * 2 + 0] + b0v;
                v.y = acc[ma][na][half * 2 + 1] + b1v;
                if (MODE == 0) {
                    int bb  = m >> 11, t = m & (T_ - 1);
                    int sec = n >> 10, rem = n & 1023;
                    int h = rem >> 6, d = rem & 63;
                    size_t idx = ((size_t)(bb * H_ + h) * T_ + t) * D_ + d;
                    if (sec == 0) { v.x *= SCALE; v.y *= SCALE; *(float2*)&g_Q[idx] = v; }
                    else if (sec == 1) { *(float2*)&g_K[idx] = v; }
                    else               { *(float2*)&g_V[idx] = v; }
                } else {
                    *(float2*)&C[(size_t)m * N2 + n] = v;
                }
            }
        }
    }
}

// ================= Attention (3xBF16 flash) ================================
// 256 threads = 8 warps, Br=128 (16 rows/warp), Bc=64.
// Ks: [64 keys][32 d-pairs]  (B-frag for S)
// Vs: [32 key-pairs][64 d]   (B-frag for PV)
// Ps: [128 rows][32 key-pairs] (A-frag for PV; per-warp private rows)
#define KSs 36
#define VSs 68
#define PSs 36
#define ATTN_WORDS (2*64*KSs + 2*32*VSs + 2*128*PSs)
#define ATTN_SMEM  (ATTN_WORDS * 4)

__global__ __launch_bounds__(256, 2) void attnb()
{
    extern __shared__ uint32_t sm[];
    uint32_t* Ks_hi = sm;
    uint32_t* Ks_lo = Ks_hi + 64 * KSs;
    uint32_t* Vs_hi = Ks_lo + 64 * KSs;
    uint32_t* Vs_lo = Vs_hi + 32 * VSs;
    uint32_t* Ps_hi = Vs_lo + 32 * VSs;
    uint32_t* Ps_lo = Ps_hi + 128 * PSs;

    const int tid = threadIdx.x, warp = tid >> 5, lane = tid & 31;
    const int g = lane >> 2, tg = lane & 3;
    const int qb = blockIdx.x, bh = blockIdx.y;
    const int wrow = warp * 16;
    const int qr0  = qb * 128 + wrow;

    const float* __restrict__ Qg = g_Q + (size_t)bh * T_ * D_;
    const float* __restrict__ Kg = g_K + (size_t)bh * T_ * D_;
    const float* __restrict__ Vg = g_V + (size_t)bh * T_ * D_;

    // Q fragments (A-frags, k16 chunks over d)
    uint32_t qfh[4][4], qfl[4][4];
#pragma unroll
    for (int ka = 0; ka < 4; ka++) {
        int c = ka * 16 + tg * 2;
        const float* r0 = &Qg[(size_t)(qr0 + g) * D_];
        const float* r8 = &Qg[(size_t)(qr0 + g + 8) * D_];
        split2(r0[c],     r0[c + 1], qfh[ka][0], qfl[ka][0]);
        split2(r8[c],     r8[c + 1], qfh[ka][1], qfl[ka][1]);
        split2(r0[c + 8], r0[c + 9], qfh[ka][2], qfl[ka][2]);
        split2(r8[c + 8], r8[c + 9], qfh[ka][3], qfl[ka][3]);
    }

    float of[8][4];
#pragma unroll
    for (int j = 0; j < 8; j++)
#pragma unroll
        for (int r = 0; r < 4; r++) of[j][r] = 0.f;

    const float NEG_INF = __int_as_float(0xff800000);
    float mrow[2] = {NEG_INF, NEG_INF};
    float lrow[2] = {0.f, 0.f};

    const int ntiles = 2 * qb + 2;
    for (int kt = 0; kt < ntiles; kt++) {
        const int base = kt * 64;
        __syncthreads();
        // K tile: 64x64 floats = 1024 float4
        for (int i = tid; i < 1024; i += 256) {
            int r = i >> 4, c4 = i & 15;
            float4 kv = *(const float4*)&Kg[(size_t)(base + r) * D_ + 4 * c4];
            uint2 h, l;
            split2(kv.x, kv.y, h.x, l.x);
            split2(kv.z, kv.w, h.y, l.y);
            *(uint2*)&Ks_hi[r * KSs + 2 * c4] = h;
            *(uint2*)&Ks_lo[r * KSs + 2 * c4] = l;
        }
        // V tile: pack key-pairs: 512 pair-ops
        for (int i = tid; i < 512; i += 256) {
            int kp = i >> 4, c4 = i & 15;
            float4 v0 = *(const float4*)&Vg[(size_t)(base + 2 * kp)     * D_ + 4 * c4];
            float4 v1 = *(const float4*)&Vg[(size_t)(base + 2 * kp + 1) * D_ + 4 * c4];
            uint4 h, l;
            split2(v0.x, v1.x, h.x, l.x);
            split2(v0.y, v1.y, h.y, l.y);
            split2(v0.z, v1.z, h.z, l.z);
            split2(v0.w, v1.w, h.w, l.w);
            *(uint4*)&Vs_hi[kp * VSs + 4 * c4] = h;
            *(uint4*)&Vs_lo[kp * VSs + 4 * c4] = l;
        }
        __syncthreads();

        if (base > qr0 + 15) continue;   // tile fully above this warp's diagonal

        // ---- S = Q K^T ----
        float sacc[8][4];
#pragma unroll
        for (int j = 0; j < 8; j++)
#pragma unroll
            for (int r = 0; r < 4; r++) sacc[j][r] = 0.f;

#pragma unroll
        for (int ka = 0; ka < 4; ka++) {
            int c = ka * 8 + tg;
#pragma unroll
            for (int na = 0; na < 8; na++) {
                int row = (na * 8 + g) * KSs;
                uint32_t bh2[2], bl2[2];
                bh2[0] = Ks_hi[row + c];  bh2[1] = Ks_hi[row + c + 4];
                bl2[0] = Ks_lo[row + c];  bl2[1] = Ks_lo[row + c + 4];
                mma16(sacc[na], qfh[ka], bh2);
                mma16(sacc[na], qfl[ka], bh2);
                mma16(sacc[na], qfh[ka], bl2);
            }
        }

        // ---- causal mask ----
        if (base + 63 > qr0) {
#pragma unroll
            for (int na = 0; na < 8; na++)
#pragma unroll
                for (int r = 0; r < 4; r++) {
                    int q = qr0 + g + (r >> 1) * 8;
                    int j = base + na * 8 + tg * 2 + (r & 1);
                    if (j > q) sacc[na][r] = NEG_INF;
                }
        }

        // ---- online softmax ----
#pragma unroll
        for (int h = 0; h < 2; h++) {
            float rm = NEG_INF;
#pragma unroll
            for (int na = 0; na < 8; na++) {
                rm = fmaxf(rm, sacc[na][h * 2 + 0]);
                rm = fmaxf(rm, sacc[na][h * 2 + 1]);
            }
            rm = fmaxf(rm, __shfl_xor_sync(0xffffffffu, rm, 1));
            rm = fmaxf(rm, __shfl_xor_sync(0xffffffffu, rm, 2));
            float mn   = fmaxf(mrow[h], rm);
            float corr = __expf(mrow[h] - mn);
            mrow[h] = mn;
            float sum = 0.f;
#pragma unroll
            for (int na = 0; na < 8; na++) {
                float p0 = __expf(sacc[na][h * 2 + 0] - mn);
                float p1 = __expf(sacc[na][h * 2 + 1] - mn);
                sacc[na][h * 2 + 0] = p0;
                sacc[na][h * 2 + 1] = p1;
                sum += p0 + p1;
            }
            sum += __shfl_xor_sync(0xffffffffu, sum, 1);
            sum += __shfl_xor_sync(0xffffffffu, sum, 2);
            lrow[h] = lrow[h] * corr + sum;
#pragma unroll
            for (int na = 0; na < 8; na++) {
                of[na][h * 2 + 0] *= corr;
                of[na][h * 2 + 1] *= corr;
            }
        }

        // ---- store P (key-pairs packed) into per-warp rows ----
#pragma unroll
        for (int na = 0; na < 8; na++) {
            int q = wrow + g;
            int c = na * 4 + tg;
            uint32_t h0, l0, h1, l1;
            split2(sacc[na][0], sacc[na][1], h0, l0);
            split2(sacc[na][2], sacc[na][3], h1, l1);
            Ps_hi[q * PSs + c]       = h0;  Ps_lo[q * PSs + c]       = l0;
            Ps_hi[(q + 8) * PSs + c] = h1;  Ps_lo[(q + 8) * PSs + c] = l1;
        }
        __syncwarp();

        // ---- O += P V ----
#pragma unroll
        for (int ka = 0; ka < 4; ka++) {
            int c = ka * 8 + tg;
            int r = wrow + g;
            uint32_t pah[4], pal[4];
            pah[0] = Ps_hi[r * PSs + c];           pal[0] = Ps_lo[r * PSs + c];
            pah[1] = Ps_hi[(r + 8) * PSs + c];     pal[1] = Ps_lo[(r + 8) * PSs + c];
            pah[2] = Ps_hi[r * PSs + c + 4];       pal[2] = Ps_lo[r * PSs + c + 4];
            pah[3] = Ps_hi[(r + 8) * PSs + c + 4]; pal[3] = Ps_lo[(r + 8) * PSs + c + 4];
#pragma unroll
            for (int na = 0; na < 8; na++) {
                int nn = na * 8 + g;
                uint32_t vh2[2], vl2[2];
                vh2[0] = Vs_hi[(ka * 8 + tg) * VSs + nn];
                vh2[1] = Vs_hi[(ka * 8 + tg + 4) * VSs + nn];
                vl2[0] = Vs_lo[(ka * 8 + tg) * VSs + nn];
                vl2[1] = Vs_lo[(ka * 8 + tg + 4) * VSs + nn];
                mma16(of[na], pah, vh2);
                mma16(of[na], pal, vh2);
                mma16(of[na], pah, vl2);
            }
        }
    }

    // ---- finalize ----
    const int bb = bh >> 4, hh = bh & 15;
    float inv0 = 1.f / lrow[0];
    float inv1 = 1.f / lrow[1];
    int q = qb * 128 + wrow + g;
    float* o0 = g_O + ((size_t)(bb * T_ + q)) * EMB + hh * D_;
    float* o8 = g_O + ((size_t)(bb * T_ + q + 8)) * EMB + hh * D_;
#pragma unroll
    for (int na = 0; na < 8; na++) {
        int d = na * 8 + tg * 2;
        float2 v0, v1;
        v0.x = of[na][0] * inv0; v0.y = of[na][1] * inv0;
        v1.x = of[na][2] * inv1; v1.y = of[na][3] * inv1;
        *(float2*)&o0[d] = v0;
        *(float2*)&o8[d] = v1;
    }
}

// ---------------- launch ----------------
extern "C" void kernel_launch(void* const* d_in, const int* in_sizes, int n_in,
                              void* d_out, int out_size)
{
    const float* x    = (const float*)d_in[0];
    const float* Wqkv = (const float*)d_in[1];
    const float* bqkv = (const float*)d_in[2];
    const float* Wout = (const float*)d_in[3];
    const float* bout = (const float*)d_in[4];
    float* out = (float*)d_out;

    static bool attr_done = false;
    if (!attr_done) {
        cudaFuncSetAttribute(attnb, cudaFuncAttributeMaxDynamicSharedMemorySize, ATTN_SMEM);
        attr_done = true;
    }

    dim3 g1(N1 / 128, M_ / 128);   // (24, 32)
    gemmb<N1, 0><<<g1, 256>>>(x, Wqkv, bqkv, nullptr);

    dim3 ga(T_ / 128, B_ * H_);    // (16, 32)
    attnb<<<ga, 256, ATTN_SMEM>>>();

    dim3 g2(N2 / 128, M_ / 128);   // (8, 32)
    gemmb<N2, 1><<<g2, 256>>>(nullptr, Wout, bout, out);
}

// round 5
// speedup vs baseline: 3.5261x; 1.0858x over previous
#include <cuda_runtime.h>
#include <cuda_bf16.h>
#include <math.h>
#include <stdint.h>

#define B_  2
#define T_  2048
#define EMB 1024
#define H_  16
#define D_  64
#define M_  (B_ * T_)          // 4096
#define N1  3072
#define N2  1024
#define SCALE 0.125f

// ---------------- scratch (u32 = bf16x2 pairs over k) ----------------
__device__ uint32_t g_xh[4096 * 512], g_xl[4096 * 512];
__device__ uint32_t g_wqh[512 * 3072], g_wql[512 * 3072];
__device__ uint32_t g_woh[512 * 1024], g_wol[512 * 1024];
__device__ uint32_t g_Qh[2097152], g_Ql[2097152];   // [BH][T][32 dpairs]
__device__ uint32_t g_Kh[2097152], g_Kl[2097152];   // [BH][T][32 dpairs]
__device__ uint32_t g_Vh[2097152], g_Vl[2097152];   // [BH][T/2][64 d] t-pair packed
__device__ uint32_t g_Oh[2097152], g_Ol[2097152];   // [M][512 pairs]

// ---------------- helpers ----------------
__device__ __forceinline__ uint32_t pack2(float x, float y) {
    uint32_t r;
    asm("cvt.rn.bf16x2.f32 %0, %1, %2;" : "=r"(r) : "f"(y), "f"(x));  // low=x, high=y
    return r;
}
__device__ __forceinline__ void split2(float x, float y, uint32_t& hi, uint32_t& lo) {
    hi = pack2(x, y);
    __nv_bfloat162 h = *reinterpret_cast<__nv_bfloat162*>(&hi);
    lo = pack2(x - __bfloat162float(h.x), y - __bfloat162float(h.y));
}
__device__ __forceinline__ void mma16(float* c, const uint32_t* a, const uint32_t* b) {
    asm volatile(
        "mma.sync.aligned.m16n8k16.row.col.f32.bf16.bf16.f32 "
        "{%0,%1,%2,%3},{%4,%5,%6,%7},{%8,%9},{%0,%1,%2,%3};\n"
        : "+f"(c[0]), "+f"(c[1]), "+f"(c[2]), "+f"(c[3])
        : "r"(a[0]), "r"(a[1]), "r"(a[2]), "r"(a[3]), "r"(b[0]), "r"(b[1]));
}
__device__ __forceinline__ uint32_t sptr(const void* p) {
    return (uint32_t)__cvta_generic_to_shared(p);
}
__device__ __forceinline__ void cp16(uint32_t saddr, const void* g) {
    asm volatile("cp.async.cg.shared.global [%0], [%1], 16;\n" :: "r"(saddr), "l"(g));
}
#define CP_COMMIT() asm volatile("cp.async.commit_group;\n" ::)
#define CP_WAIT0()  asm volatile("cp.async.wait_group 0;\n" ::)
#define CP_WAIT1()  asm volatile("cp.async.wait_group 1;\n" ::)

// ---------------- prep: fp32 -> bf16 hi/lo ----------------
__global__ __launch_bounds__(256) void prep_x(const float* __restrict__ x) {
    int i = blockIdx.x * 256 + threadIdx.x;            // < 4096*512
    float2 v = ((const float2*)x)[i];
    split2(v.x, v.y, g_xh[i], g_xl[i]);
}

template<int N, int SEL>
__global__ __launch_bounds__(256) void prep_w(const float* __restrict__ W) {
    int n  = blockIdx.x * 256 + threadIdx.x;
    int kp = blockIdx.y;
    float a = W[(size_t)(2 * kp) * N + n];
    float b = W[(size_t)(2 * kp + 1) * N + n];
    uint32_t h, l;
    split2(a, b, h, l);
    if (SEL == 0) { g_wqh[kp * N + n] = h; g_wql[kp * N + n] = l; }
    else          { g_woh[kp * N + n] = h; g_wol[kp * N + n] = l; }
}

// ================= GEMM (3xBF16, cp.async double-buffered) =================
// Block 128x128, 8 warps (2x4), warp tile 64x32, BK=32 (16 kpairs).
#define AS_STR 20
#define BS_STR 136
#define ASL_OFF 2560              // 128*20
#define BSH_OFF 5120
#define BSL_OFF 7296              // 5120 + 16*136
#define STAGE_WORDS 9472
#define GEMM_SMEM (2 * STAGE_WORDS * 4)

template<int N, int MODE>
__device__ __forceinline__ void g_load_stage(uint32_t* st, int kb, int bm, int bn, int tid,
                                             const uint32_t* Ah, const uint32_t* Al,
                                             const uint32_t* Wh, const uint32_t* Wl)
{
#pragma unroll
    for (int j = 0; j < 2; j++) {
        int idx = tid + j * 256;
        int row = idx >> 2, c = (idx & 3) * 4;
        size_t src = (size_t)(bm + row) * 512 + kb * 16 + c;
        cp16(sptr(&st[row * AS_STR + c]), &Ah[src]);
        cp16(sptr(&st[ASL_OFF + row * AS_STR + c]), &Al[src]);
    }
#pragma unroll
    for (int j = 0; j < 2; j++) {
        int idx = tid + j * 256;
        int r = idx >> 5, c = (idx & 31) * 4;
        size_t src = (size_t)(kb * 16 + r) * N + bn + c;
        cp16(sptr(&st[BSH_OFF + r * BS_STR + c]), &Wh[src]);
        cp16(sptr(&st[BSL_OFF + r * BS_STR + c]), &Wl[src]);
    }
}

template<int N, int MODE>
__global__ __launch_bounds__(256, 2) void gemmb(const float* __restrict__ bias,
                                                float* __restrict__ C)
{
    extern __shared__ uint32_t smem_g[];
    const uint32_t* Ah = (MODE == 0) ? g_xh  : g_Oh;
    const uint32_t* Al = (MODE == 0) ? g_xl  : g_Ol;
    const uint32_t* Wh = (MODE == 0) ? g_wqh : g_woh;
    const uint32_t* Wl = (MODE == 0) ? g_wql : g_wol;

    const int tid  = threadIdx.x;
    const int warp = tid >> 5, lane = tid & 31;
    const int g    = lane >> 2, tg = lane & 3;
    const int wy   = warp >> 2, wx = warp & 3;
    const int bm   = blockIdx.y * 128, bn = blockIdx.x * 128;

    float acc[4][4][4];
#pragma unroll
    for (int i = 0; i < 4; i++)
#pragma unroll
        for (int j = 0; j < 4; j++)
#pragma unroll
            for (int r = 0; r < 4; r++) acc[i][j][r] = 0.f;

    uint32_t* st0 = smem_g;
    uint32_t* st1 = smem_g + STAGE_WORDS;

    g_load_stage<N, MODE>(st0, 0, bm, bn, tid, Ah, Al, Wh, Wl);
    CP_COMMIT();
    g_load_stage<N, MODE>(st1, 1, bm, bn, tid, Ah, Al, Wh, Wl);
    CP_COMMIT();

    for (int kb = 0; kb < 32; kb++) {
        CP_WAIT1();
        __syncthreads();
        uint32_t* st = (kb & 1) ? st1 : st0;

#pragma unroll
        for (int ka = 0; ka < 2; ka++) {
            uint32_t bfh[4][2], bfl[4][2];
#pragma unroll
            for (int na = 0; na < 4; na++) {
                int cN = wx * 32 + na * 8 + g;
                int r0 = (ka * 8 + tg) * BS_STR, r4 = (ka * 8 + tg + 4) * BS_STR;
                bfh[na][0] = st[BSH_OFF + r0 + cN];
                bfh[na][1] = st[BSH_OFF + r4 + cN];
                bfl[na][0] = st[BSL_OFF + r0 + cN];
                bfl[na][1] = st[BSL_OFF + r4 + cN];
            }
#pragma unroll
            for (int ma = 0; ma < 4; ma++) {
                int r = wy * 64 + ma * 16 + g;
                int c0 = ka * 8 + tg;
                uint32_t afh[4], afl[4];
                afh[0] = st[r * AS_STR + c0];
                afh[1] = st[(r + 8) * AS_STR + c0];
                afh[2] = st[r * AS_STR + c0 + 4];
                afh[3] = st[(r + 8) * AS_STR + c0 + 4];
                afl[0] = st[ASL_OFF + r * AS_STR + c0];
                afl[1] = st[ASL_OFF + (r + 8) * AS_STR + c0];
                afl[2] = st[ASL_OFF + r * AS_STR + c0 + 4];
                afl[3] = st[ASL_OFF + (r + 8) * AS_STR + c0 + 4];
#pragma unroll
                for (int na = 0; na < 4; na++) {
                    mma16(acc[ma][na], afh, bfh[na]);
                    mma16(acc[ma][na], afl, bfh[na]);
                    mma16(acc[ma][na], afh, bfl[na]);
                }
            }
        }
        __syncthreads();
        if (kb + 2 < 32)
            g_load_stage<N, MODE>(st, kb + 2, bm, bn, tid, Ah, Al, Wh, Wl);
        CP_COMMIT();
    }

    // ---------- epilogue ----------
#pragma unroll
    for (int ma = 0; ma < 4; ma++) {
        int m0 = bm + wy * 64 + ma * 16 + g;
#pragma unroll
        for (int na = 0; na < 4; na++) {
            int n = bn + wx * 32 + na * 8 + tg * 2;
            float b0v = bias[n], b1v = bias[n + 1];
#pragma unroll
            for (int half = 0; half < 2; half++) {
                int m = m0 + half * 8;
                float vx = acc[ma][na][half * 2 + 0] + b0v;
                float vy = acc[ma][na][half * 2 + 1] + b1v;
                if (MODE == 0) {
                    int bb  = m >> 11, t = m & (T_ - 1);
                    int sec = n >> 10, rem = n & 1023;
                    int h = rem >> 6, d = rem & 63;
                    int bhh = bb * H_ + h;
                    if (sec == 0) {
                        vx *= SCALE; vy *= SCALE;
                        uint32_t hi, lo;
                        split2(vx, vy, hi, lo);
                        size_t idx = ((size_t)bhh * T_ + t) * 32 + (d >> 1);
                        g_Qh[idx] = hi; g_Ql[idx] = lo;
                    } else if (sec == 1) {
                        uint32_t hi, lo;
                        split2(vx, vy, hi, lo);
                        size_t idx = ((size_t)bhh * T_ + t) * 32 + (d >> 1);
                        g_Kh[idx] = hi; g_Kl[idx] = lo;
                    } else {
                        __nv_bfloat16 hx = __float2bfloat16(vx);
                        __nv_bfloat16 hy = __float2bfloat16(vy);
                        __nv_bfloat16 lx = __float2bfloat16(vx - __bfloat162float(hx));
                        __nv_bfloat16 ly = __float2bfloat16(vy - __bfloat162float(hy));
                        size_t base = (((size_t)bhh * 1024 + (t >> 1)) * 64 + d) * 2 + (t & 1);
                        __nv_bfloat16* Vh = reinterpret_cast<__nv_bfloat16*>(g_Vh);
                        __nv_bfloat16* Vl = reinterpret_cast<__nv_bfloat16*>(g_Vl);
                        Vh[base] = hx; Vh[base + 2] = hy;
                        Vl[base] = lx; Vl[base + 2] = ly;
                    }
                } else {
                    float2 v; v.x = vx; v.y = vy;
                    *(float2*)&C[(size_t)m * N2 + n] = v;
                }
            }
        }
    }
}

// ================= Attention (3xBF16 flash, cp.async tiles) ================
#define KSs 36
#define VSs 72
#define PSs 36
#define ATTN_WORDS (2*64*KSs + 2*32*VSs + 2*128*PSs)   // 18432
#define ATTN_SMEM  (ATTN_WORDS * 4)

__global__ __launch_bounds__(256, 2) void attnb()
{
    extern __shared__ uint32_t sm[];
    uint32_t* Ks_hi = sm;
    uint32_t* Ks_lo = Ks_hi + 64 * KSs;
    uint32_t* Vs_hi = Ks_lo + 64 * KSs;
    uint32_t* Vs_lo = Vs_hi + 32 * VSs;
    uint32_t* Ps_hi = Vs_lo + 32 * VSs;
    uint32_t* Ps_lo = Ps_hi + 128 * PSs;

    const int tid = threadIdx.x, warp = tid >> 5, lane = tid & 31;
    const int g = lane >> 2, tg = lane & 3;
    const int qb = blockIdx.x, bh = blockIdx.y;
    const int wrow = warp * 16;
    const int qr0  = qb * 128 + wrow;

    // Q fragments (u32 = dpair) straight from gmem
    uint32_t qfh[4][4], qfl[4][4];
    {
        size_t r0 = ((size_t)bh * T_ + qr0 + g) * 32;
        size_t r8 = r0 + 8 * 32;
#pragma unroll
        for (int ka = 0; ka < 4; ka++) {
            int kp = ka * 8 + tg;
            qfh[ka][0] = g_Qh[r0 + kp];     qfl[ka][0] = g_Ql[r0 + kp];
            qfh[ka][1] = g_Qh[r8 + kp];     qfl[ka][1] = g_Ql[r8 + kp];
            qfh[ka][2] = g_Qh[r0 + kp + 4]; qfl[ka][2] = g_Ql[r0 + kp + 4];
            qfh[ka][3] = g_Qh[r8 + kp + 4]; qfl[ka][3] = g_Ql[r8 + kp + 4];
        }
    }

    float of[8][4];
#pragma unroll
    for (int j = 0; j < 8; j++)
#pragma unroll
        for (int r = 0; r < 4; r++) of[j][r] = 0.f;

    const float NEG_INF = __int_as_float(0xff800000);
    float mrow[2] = {NEG_INF, NEG_INF};
    float lrow[2] = {0.f, 0.f};

    const int ntiles = 2 * qb + 2;
    for (int kt = 0; kt < ntiles; kt++) {
        const int base = kt * 64;
        __syncthreads();   // previous-tile consumers done
        // K tile: 64 rows x 32 u32 (hi+lo)
#pragma unroll
        for (int j = 0; j < 2; j++) {
            int i = tid + j * 256;            // 0..511
            int r = i >> 3, c = (i & 7) * 4;
            size_t src = ((size_t)bh * T_ + base + r) * 32 + c;
            cp16(sptr(&Ks_hi[r * KSs + c]), &g_Kh[src]);
            cp16(sptr(&Ks_lo[r * KSs + c]), &g_Kl[src]);
        }
        // V tile: 32 kp rows x 64 u32 (hi+lo)
#pragma unroll
        for (int j = 0; j < 2; j++) {
            int i = tid + j * 256;
            int r = i >> 4, c = (i & 15) * 4;
            size_t src = ((size_t)bh * 1024 + (base >> 1) + r) * 64 + c;
            cp16(sptr(&Vs_hi[r * VSs + c]), &g_Vh[src]);
            cp16(sptr(&Vs_lo[r * VSs + c]), &g_Vl[src]);
        }
        CP_COMMIT();
        CP_WAIT0();
        __syncthreads();

        if (base > qr0 + 15) continue;

        // ---- S = Q K^T ----
        float sacc[8][4];
#pragma unroll
        for (int j = 0; j < 8; j++)
#pragma unroll
            for (int r = 0; r < 4; r++) sacc[j][r] = 0.f;

#pragma unroll
        for (int ka = 0; ka < 4; ka++) {
            int c = ka * 8 + tg;
#pragma unroll
            for (int na = 0; na < 8; na++) {
                int row = (na * 8 + g) * KSs;
                uint32_t bh2[2], bl2[2];
                bh2[0] = Ks_hi[row + c];  bh2[1] = Ks_hi[row + c + 4];
                bl2[0] = Ks_lo[row + c];  bl2[1] = Ks_lo[row + c + 4];
                mma16(sacc[na], qfh[ka], bh2);
                mma16(sacc[na], qfl[ka], bh2);
                mma16(sacc[na], qfh[ka], bl2);
            }
        }

        // ---- causal mask ----
        if (base + 63 > qr0) {
#pragma unroll
            for (int na = 0; na < 8; na++)
#pragma unroll
                for (int r = 0; r < 4; r++) {
                    int q = qr0 + g + (r >> 1) * 8;
                    int j = base + na * 8 + tg * 2 + (r & 1);
                    if (j > q) sacc[na][r] = NEG_INF;
                }
        }

        // ---- online softmax ----
#pragma unroll
        for (int h = 0; h < 2; h++) {
            float rm = NEG_INF;
#pragma unroll
            for (int na = 0; na < 8; na++) {
                rm = fmaxf(rm, sacc[na][h * 2 + 0]);
                rm = fmaxf(rm, sacc[na][h * 2 + 1]);
            }
            rm = fmaxf(rm, __shfl_xor_sync(0xffffffffu, rm, 1));
            rm = fmaxf(rm, __shfl_xor_sync(0xffffffffu, rm, 2));
            float mn   = fmaxf(mrow[h], rm);
            float corr = __expf(mrow[h] - mn);
            mrow[h] = mn;
            float sum = 0.f;
#pragma unroll
            for (int na = 0; na < 8; na++) {
                float p0 = __expf(sacc[na][h * 2 + 0] - mn);
                float p1 = __expf(sacc[na][h * 2 + 1] - mn);
                sacc[na][h * 2 + 0] = p0;
                sacc[na][h * 2 + 1] = p1;
                sum += p0 + p1;
            }
            sum += __shfl_xor_sync(0xffffffffu, sum, 1);
            sum += __shfl_xor_sync(0xffffffffu, sum, 2);
            lrow[h] = lrow[h] * corr + sum;
#pragma unroll
            for (int na = 0; na < 8; na++) {
                of[na][h * 2 + 0] *= corr;
                of[na][h * 2 + 1] *= corr;
            }
        }

        // ---- store P (key-pairs packed) ----
#pragma unroll
        for (int na = 0; na < 8; na++) {
            int q = wrow + g;
            int c = na * 4 + tg;
            uint32_t h0, l0, h1, l1;
            split2(sacc[na][0], sacc[na][1], h0, l0);
            split2(sacc[na][2], sacc[na][3], h1, l1);
            Ps_hi[q * PSs + c]       = h0;  Ps_lo[q * PSs + c]       = l0;
            Ps_hi[(q + 8) * PSs + c] = h1;  Ps_lo[(q + 8) * PSs + c] = l1;
        }
        __syncwarp();

        // ---- O += P V ----
#pragma unroll
        for (int ka = 0; ka < 4; ka++) {
            int c = ka * 8 + tg;
            int r = wrow + g;
            uint32_t pah[4], pal[4];
            pah[0] = Ps_hi[r * PSs + c];           pal[0] = Ps_lo[r * PSs + c];
            pah[1] = Ps_hi[(r + 8) * PSs + c];     pal[1] = Ps_lo[(r + 8) * PSs + c];
            pah[2] = Ps_hi[r * PSs + c + 4];       pal[2] = Ps_lo[r * PSs + c + 4];
            pah[3] = Ps_hi[(r + 8) * PSs + c + 4]; pal[3] = Ps_lo[(r + 8) * PSs + c + 4];
#pragma unroll
            for (int na = 0; na < 8; na++) {
                int nn = na * 8 + g;
                uint32_t vh2[2], vl2[2];
                vh2[0] = Vs_hi[(ka * 8 + tg) * VSs + nn];
                vh2[1] = Vs_hi[(ka * 8 + tg + 4) * VSs + nn];
                vl2[0] = Vs_lo[(ka * 8 + tg) * VSs + nn];
                vl2[1] = Vs_lo[(ka * 8 + tg + 4) * VSs + nn];
                mma16(of[na], pah, vh2);
                mma16(of[na], pal, vh2);
                mma16(of[na], pah, vl2);
            }
        }
    }

    // ---- finalize: write O hi/lo bf16 pairs ----
    const int bb = bh >> 4, hh = bh & 15;
    float inv0 = 1.f / lrow[0];
    float inv1 = 1.f / lrow[1];
    int q = qb * 128 + wrow + g;
    size_t r0 = (size_t)(bb * T_ + q) * 512 + hh * 32;
    size_t r8 = r0 + 8 * 512;
#pragma unroll
    for (int na = 0; na < 8; na++) {
        int dp = (na * 8 + tg * 2) >> 1;
        uint32_t h0, l0, h1, l1;
        split2(of[na][0] * inv0, of[na][1] * inv0, h0, l0);
        split2(of[na][2] * inv1, of[na][3] * inv1, h1, l1);
        g_Oh[r0 + dp] = h0;  g_Ol[r0 + dp] = l0;
        g_Oh[r8 + dp] = h1;  g_Ol[r8 + dp] = l1;
    }
}

// ---------------- launch ----------------
extern "C" void kernel_launch(void* const* d_in, const int* in_sizes, int n_in,
                              void* d_out, int out_size)
{
    const float* x    = (const float*)d_in[0];
    const float* Wqkv = (const float*)d_in[1];
    const float* bqkv = (const float*)d_in[2];
    const float* Wout = (const float*)d_in[3];
    const float* bout = (const float*)d_in[4];
    float* out = (float*)d_out;

    static bool attr_done = false;
    if (!attr_done) {
        cudaFuncSetAttribute((void*)gemmb<N1, 0>, cudaFuncAttributeMaxDynamicSharedMemorySize, GEMM_SMEM);
        cudaFuncSetAttribute((void*)gemmb<N2, 1>, cudaFuncAttributeMaxDynamicSharedMemorySize, GEMM_SMEM);
        cudaFuncSetAttribute((void*)attnb,        cudaFuncAttributeMaxDynamicSharedMemorySize, ATTN_SMEM);
        attr_done = true;
    }

    prep_x<<<4096 * 512 / 256, 256>>>(x);
    prep_w<N1, 0><<<dim3(N1 / 256, 512), 256>>>(Wqkv);
    prep_w<N2, 1><<<dim3(N2 / 256, 512), 256>>>(Wout);

    dim3 g1(N1 / 128, M_ / 128);   // (24, 32)
    gemmb<N1, 0><<<g1, 256, GEMM_SMEM>>>(bqkv, nullptr);

    dim3 ga(T_ / 128, B_ * H_);    // (16, 32)
    attnb<<<ga, 256, ATTN_SMEM>>>();

    dim3 g2(N2 / 128, M_ / 128);   // (8, 32)
    gemmb<N2, 1><<<g2, 256, GEMM_SMEM>>>(bout, out);
}

// round 6
// speedup vs baseline: 3.6500x; 1.0351x over previous
#include <cuda_runtime.h>
#include <cuda_bf16.h>
#include <math.h>
#include <stdint.h>

#define B_  2
#define T_  2048
#define EMB 1024
#define H_  16
#define D_  64
#define M_  (B_ * T_)          // 4096
#define N1  3072
#define N2  1024
#define SCALE 0.125f

// ---------------- scratch (u32 = bf16x2) ----------------
__device__ uint32_t g_xh[4096 * 512], g_xl[4096 * 512];     // x  [m][kpair]
__device__ uint32_t g_wqh[3072 * 512], g_wql[3072 * 512];   // Wqkv^T [n][kpair]
__device__ uint32_t g_woh[1024 * 512], g_wol[1024 * 512];   // Wout^T [n][kpair]
__device__ uint32_t g_Qh[2097152], g_Ql[2097152];           // [bh][t][32 dpair]
__device__ uint32_t g_Kh[2097152], g_Kl[2097152];           // [bh][t][32 dpair]
__device__ uint32_t g_Vh[2097152], g_Vl[2097152];           // [bh][64 d][1024 tpair]
__device__ uint32_t g_Oh[2097152], g_Ol[2097152];           // [m][512 kpair]

// ---------------- helpers ----------------
__device__ __forceinline__ uint32_t pack2(float x, float y) {
    uint32_t r;
    asm("cvt.rn.bf16x2.f32 %0, %1, %2;" : "=r"(r) : "f"(y), "f"(x));  // low=x, high=y
    return r;
}
__device__ __forceinline__ void split2(float x, float y, uint32_t& hi, uint32_t& lo) {
    hi = pack2(x, y);
    __nv_bfloat162 h = *reinterpret_cast<__nv_bfloat162*>(&hi);
    lo = pack2(x - __bfloat162float(h.x), y - __bfloat162float(h.y));
}
__device__ __forceinline__ void mma16(float* c, const uint32_t* a, const uint32_t* b) {
    asm volatile(
        "mma.sync.aligned.m16n8k16.row.col.f32.bf16.bf16.f32 "
        "{%0,%1,%2,%3},{%4,%5,%6,%7},{%8,%9},{%0,%1,%2,%3};\n"
        : "+f"(c[0]), "+f"(c[1]), "+f"(c[2]), "+f"(c[3])
        : "r"(a[0]), "r"(a[1]), "r"(a[2]), "r"(a[3]), "r"(b[0]), "r"(b[1]));
}
__device__ __forceinline__ void ldsm4(uint32_t* r, uint32_t saddr) {
    asm volatile("ldmatrix.sync.aligned.m8n8.x4.shared.b16 {%0,%1,%2,%3}, [%4];"
                 : "=r"(r[0]), "=r"(r[1]), "=r"(r[2]), "=r"(r[3]) : "r"(saddr));
}
__device__ __forceinline__ uint32_t sptr(const void* p) {
    return (uint32_t)__cvta_generic_to_shared(p);
}
__device__ __forceinline__ void cp16(uint32_t saddr, const void* g) {
    asm volatile("cp.async.cg.shared.global [%0], [%1], 16;\n" :: "r"(saddr), "l"(g));
}
#define CP_COMMIT() asm volatile("cp.async.commit_group;\n" ::)
#define CP_WAIT1()  asm volatile("cp.async.wait_group 1;\n" ::)

// ---------------- prep kernels ----------------
__global__ __launch_bounds__(256) void prep_x(const float* __restrict__ x) {
    int i = blockIdx.x * 256 + threadIdx.x;
    float2 v = ((const float2*)x)[i];
    split2(v.x, v.y, g_xh[i], g_xl[i]);
}

// transpose W[1024 k][N n] -> Wt[n][512 kpair], split hi/lo.
// block: 64 n x 32 kpair tile.
template<int N, int SEL>
__global__ __launch_bounds__(256) void prep_w(const float* __restrict__ W) {
    __shared__ uint32_t sh[64][33], sl[64][33];
    const int tid = threadIdx.x;
    const int n0 = blockIdx.x * 64, kp0 = blockIdx.y * 32;
#pragma unroll
    for (int r = 0; r < 8; r++) {
        int kp = r * 4 + (tid >> 6);
        int n  = tid & 63;
        float a = W[(size_t)(2 * (kp0 + kp))     * N + n0 + n];
        float b = W[(size_t)(2 * (kp0 + kp) + 1) * N + n0 + n];
        split2(a, b, sh[n][kp], sl[n][kp]);
    }
    __syncthreads();
    uint32_t* Dh = (SEL == 0) ? g_wqh : g_woh;
    uint32_t* Dl = (SEL == 0) ? g_wql : g_wol;
#pragma unroll
    for (int w = 0; w < 8; w++) {
        int n = w * 8 + (tid >> 5), c = tid & 31;
        Dh[(size_t)(n0 + n) * 512 + kp0 + c] = sh[n][c];
        Dl[(size_t)(n0 + n) * 512 + kp0 + c] = sl[n][c];
    }
}

// ================= GEMM (3xBF16, ldmatrix, cp.async 2-stage) ===============
// Block 128x128, 8 warps (2x4), warp tile 64x32, BK=32 (16 kpairs).
// smem per stage: A_hi[128][20], A_lo, B_hi[128][20], B_lo.
#define GS 20
#define G_ALO 2560
#define G_BHI 5120
#define G_BLO 7680
#define G_STAGE 10240
#define GEMM_SMEM (2 * G_STAGE * 4)

__device__ __forceinline__ void g_load_stage(uint32_t sbase, int kb, int bm, int bn, int tid,
                                             const uint32_t* __restrict__ Ah,
                                             const uint32_t* __restrict__ Al,
                                             const uint32_t* __restrict__ Wh,
                                             const uint32_t* __restrict__ Wl)
{
#pragma unroll
    for (int j = 0; j < 2; j++) {
        int idx = tid + j * 256;
        int row = idx >> 2, c = (idx & 3) * 4;
        size_t srcA = (size_t)(bm + row) * 512 + kb * 16 + c;
        size_t srcB = (size_t)(bn + row) * 512 + kb * 16 + c;
        uint32_t off = (row * GS + c) * 4;
        cp16(sbase + off,               &Ah[srcA]);
        cp16(sbase + G_ALO * 4 + off,   &Al[srcA]);
        cp16(sbase + G_BHI * 4 + off,   &Wh[srcB]);
        cp16(sbase + G_BLO * 4 + off,   &Wl[srcB]);
    }
}

template<int MODE>
__global__ __launch_bounds__(256, 2) void gemmb(const float* __restrict__ bias,
                                                float* __restrict__ C)
{
    extern __shared__ uint32_t smem_g[];
    const uint32_t* Ah = (MODE == 0) ? g_xh  : g_Oh;
    const uint32_t* Al = (MODE == 0) ? g_xl  : g_Ol;
    const uint32_t* Wh = (MODE == 0) ? g_wqh : g_woh;
    const uint32_t* Wl = (MODE == 0) ? g_wql : g_wol;

    const int tid  = threadIdx.x;
    const int warp = tid >> 5, lane = tid & 31;
    const int g    = lane >> 2, tg = lane & 3;
    const int wy   = warp >> 2, wx = warp & 3;
    const int bm   = blockIdx.y * 128, bn = blockIdx.x * 128;

    float acc[4][4][4];
#pragma unroll
    for (int i = 0; i < 4; i++)
#pragma unroll
        for (int j = 0; j < 4; j++)
#pragma unroll
            for (int r = 0; r < 4; r++) acc[i][j][r] = 0.f;

    const uint32_t sbase = sptr(smem_g);
    // ldmatrix lane offsets (u32 units within stage)
    const int a_row = wy * 64 + (lane & 15);
    const int a_col = (lane >> 4) * 4;
    const int b_row = wx * 32 + ((lane >> 4) & 1) * 8 + (lane & 7);
    const int b_col = ((lane >> 3) & 1) * 4;

    g_load_stage(sbase, 0, bm, bn, tid, Ah, Al, Wh, Wl);
    CP_COMMIT();
    g_load_stage(sbase + G_STAGE * 4, 1, bm, bn, tid, Ah, Al, Wh, Wl);
    CP_COMMIT();

    for (int kb = 0; kb < 32; kb++) {
        CP_WAIT1();
        __syncthreads();
        const uint32_t st = sbase + (kb & 1) * (G_STAGE * 4);

#pragma unroll
        for (int ka = 0; ka < 2; ka++) {
            uint32_t kbh[2][4], kbl[2][4];
#pragma unroll
            for (int nb = 0; nb < 2; nb++) {
                uint32_t off = ((b_row + nb * 16) * GS + ka * 8 + b_col) * 4;
                ldsm4(kbh[nb], st + G_BHI * 4 + off);
                ldsm4(kbl[nb], st + G_BLO * 4 + off);
            }
#pragma unroll
            for (int ma = 0; ma < 4; ma++) {
                uint32_t off = ((a_row + ma * 16) * GS + ka * 8 + a_col) * 4;
                uint32_t ah[4], al[4];
                ldsm4(ah, st + off);
                ldsm4(al, st + G_ALO * 4 + off);
#pragma unroll
                for (int na = 0; na < 4; na++) {
                    const uint32_t* b2h = &kbh[na >> 1][(na & 1) * 2];
                    const uint32_t* b2l = &kbl[na >> 1][(na & 1) * 2];
                    mma16(acc[ma][na], ah, b2h);
                    mma16(acc[ma][na], al, b2h);
                    mma16(acc[ma][na], ah, b2l);
                }
            }
        }
        __syncthreads();
        if (kb + 2 < 32)
            g_load_stage(st, kb + 2, bm, bn, tid, Ah, Al, Wh, Wl);
        CP_COMMIT();
    }

    // ---------- epilogue ----------
#pragma unroll
    for (int ma = 0; ma < 4; ma++) {
        int m0 = bm + wy * 64 + ma * 16 + g;
#pragma unroll
        for (int na = 0; na < 4; na++) {
            int n = bn + wx * 32 + na * 8 + tg * 2;
            float b0v = bias[n], b1v = bias[n + 1];
#pragma unroll
            for (int half = 0; half < 2; half++) {
                int m = m0 + half * 8;
                float vx = acc[ma][na][half * 2 + 0] + b0v;
                float vy = acc[ma][na][half * 2 + 1] + b1v;
                if (MODE == 0) {
                    int bb  = m >> 11, t = m & (T_ - 1);
                    int sec = n >> 10, rem = n & 1023;
                    int h = rem >> 6, d = rem & 63;
                    int bhh = bb * H_ + h;
                    if (sec == 0) {
                        vx *= SCALE; vy *= SCALE;
                        uint32_t hi, lo;
                        split2(vx, vy, hi, lo);
                        size_t idx = ((size_t)bhh * T_ + t) * 32 + (d >> 1);
                        g_Qh[idx] = hi; g_Ql[idx] = lo;
                    } else if (sec == 1) {
                        uint32_t hi, lo;
                        split2(vx, vy, hi, lo);
                        size_t idx = ((size_t)bhh * T_ + t) * 32 + (d >> 1);
                        g_Kh[idx] = hi; g_Kl[idx] = lo;
                    } else {
                        __nv_bfloat16 hx = __float2bfloat16(vx);
                        __nv_bfloat16 hy = __float2bfloat16(vy);
                        __nv_bfloat16 lx = __float2bfloat16(vx - __bfloat162float(hx));
                        __nv_bfloat16 ly = __float2bfloat16(vy - __bfloat162float(hy));
                        // V[d][tpair]: bf16 index = ((bhh*64 + d)*1024 + t/2)*2 + (t&1)
                        size_t ix = (((size_t)bhh * 64 + d) * 1024 + (t >> 1)) * 2 + (t & 1);
                        __nv_bfloat16* Vh = reinterpret_cast<__nv_bfloat16*>(g_Vh);
                        __nv_bfloat16* Vl = reinterpret_cast<__nv_bfloat16*>(g_Vl);
                        Vh[ix] = hx; Vh[ix + 2048] = hy;   // d+1 -> +1024 u32 = +2048 bf16
                        Vl[ix] = lx; Vl[ix + 2048] = ly;
                    }
                } else {
                    float2 v; v.x = vx; v.y = vy;
                    *(float2*)&C[(size_t)m * N2 + n] = v;
                }
            }
        }
    }
}

// ================= Attention (3xBF16 flash, ldmatrix, 2-stage) =============
// 256 threads = 8 warps, Br=128 (16 rows/warp), Bc=64.
// Stage: K_hi[64 t][36], K_lo, V_hi[64 d][36], V_lo (cols = 32 pairs + pad).
#define ATS 36
#define A_KLO 2304
#define A_VHI 4608
#define A_VLO 6912
#define A_STAGE 9216
#define ATTN_SMEM (2 * A_STAGE * 4)

__device__ __forceinline__ void a_load_stage(uint32_t sbase, int bh, int base, int tid)
{
#pragma unroll
    for (int j = 0; j < 2; j++) {
        int i = tid + j * 256;           // 0..511
        int r = i >> 3, c = (i & 7) * 4;
        uint32_t off = (r * ATS + c) * 4;
        size_t srcK = ((size_t)bh * T_ + base + r) * 32 + c;
        size_t srcV = ((size_t)bh * 64 + r) * 1024 + (base >> 1) + c;
        cp16(sbase + off,               &g_Kh[srcK]);
        cp16(sbase + A_KLO * 4 + off,   &g_Kl[srcK]);
        cp16(sbase + A_VHI * 4 + off,   &g_Vh[srcV]);
        cp16(sbase + A_VLO * 4 + off,   &g_Vl[srcV]);
    }
}

__global__ __launch_bounds__(256, 2) void attnb()
{
    extern __shared__ uint32_t sm[];
    const int tid = threadIdx.x, warp = tid >> 5, lane = tid & 31;
    const int g = lane >> 2, tg = lane & 3;
    const int qb = blockIdx.x, bh = blockIdx.y;
    const int wrow = warp * 16;
    const int qr0  = qb * 128 + wrow;

    const uint32_t sbase = sptr(sm);
    // ldmatrix lane offsets (shared by K and V regions)
    const int f_row = ((lane >> 4) & 1) * 8 + (lane & 7);
    const int f_col = ((lane >> 3) & 1) * 4;

    // Q fragments from gmem
    uint32_t qfh[4][4], qfl[4][4];
    {
        size_t r0 = ((size_t)bh * T_ + qr0 + g) * 32;
        size_t r8 = r0 + 8 * 32;
#pragma unroll
        for (int ka = 0; ka < 4; ka++) {
            int kp = ka * 8 + tg;
            qfh[ka][0] = g_Qh[r0 + kp];     qfl[ka][0] = g_Ql[r0 + kp];
            qfh[ka][1] = g_Qh[r8 + kp];     qfl[ka][1] = g_Ql[r8 + kp];
            qfh[ka][2] = g_Qh[r0 + kp + 4]; qfl[ka][2] = g_Ql[r0 + kp + 4];
            qfh[ka][3] = g_Qh[r8 + kp + 4]; qfl[ka][3] = g_Ql[r8 + kp + 4];
        }
    }

    float of[8][4];
#pragma unroll
    for (int j = 0; j < 8; j++)
#pragma unroll
        for (int r = 0; r < 4; r++) of[j][r] = 0.f;

    const float NEG_INF = __int_as_float(0xff800000);
    float mrow[2] = {NEG_INF, NEG_INF};
    float lrow[2] = {0.f, 0.f};

    const int ntiles = 2 * qb + 2;
    a_load_stage(sbase, bh, 0, tid);
    CP_COMMIT();

    for (int kt = 0; kt < ntiles; kt++) {
        const int base = kt * 64;
        __syncthreads();                       // all warps done with buf[(kt+1)&1]
        if (kt + 1 < ntiles)
            a_load_stage(sbase + ((kt + 1) & 1) * (A_STAGE * 4), bh, base + 64, tid);
        CP_COMMIT();
        CP_WAIT1();                            // tile kt resident
        __syncthreads();

        if (base > qr0 + 15) continue;
        const uint32_t st = sbase + (kt & 1) * (A_STAGE * 4);

        // ---- S = Q K^T ----
        float sacc[8][4];
#pragma unroll
        for (int j = 0; j < 8; j++)
#pragma unroll
            for (int r = 0; r < 4; r++) sacc[j][r] = 0.f;

#pragma unroll
        for (int nb = 0; nb < 4; nb++) {       // key block pairs (16 keys)
#pragma unroll
            for (int ka = 0; ka < 4; ka++) {   // dpair chunks (k16)
                uint32_t off = ((f_row + nb * 16) * ATS + ka * 8 + f_col) * 4;
                uint32_t bh4[4], bl4[4];
                ldsm4(bh4, st + off);
                ldsm4(bl4, st + A_KLO * 4 + off);
                mma16(sacc[2 * nb],     qfh[ka], &bh4[0]);
                mma16(sacc[2 * nb],     qfl[ka], &bh4[0]);
                mma16(sacc[2 * nb],     qfh[ka], &bl4[0]);
                mma16(sacc[2 * nb + 1], qfh[ka], &bh4[2]);
                mma16(sacc[2 * nb + 1], qfl[ka], &bh4[2]);
                mma16(sacc[2 * nb + 1], qfh[ka], &bl4[2]);
            }
        }

        // ---- causal mask ----
        if (base + 63 > qr0) {
#pragma unroll
            for (int na = 0; na < 8; na++)
#pragma unroll
                for (int r = 0; r < 4; r++) {
                    int q = qr0 + g + (r >> 1) * 8;
                    int j = base + na * 8 + tg * 2 + (r & 1);
                    if (j > q) sacc[na][r] = NEG_INF;
                }
        }

        // ---- online softmax ----
#pragma unroll
        for (int h = 0; h < 2; h++) {
            float rm = NEG_INF;
#pragma unroll
            for (int na = 0; na < 8; na++) {
                rm = fmaxf(rm, sacc[na][h * 2 + 0]);
                rm = fmaxf(rm, sacc[na][h * 2 + 1]);
            }
            rm = fmaxf(rm, __shfl_xor_sync(0xffffffffu, rm, 1));
            rm = fmaxf(rm, __shfl_xor_sync(0xffffffffu, rm, 2));
            float mn   = fmaxf(mrow[h], rm);
            float corr = __expf(mrow[h] - mn);
            mrow[h] = mn;
            float sum = 0.f;
#pragma unroll
            for (int na = 0; na < 8; na++) {
                float p0 = __expf(sacc[na][h * 2 + 0] - mn);
                float p1 = __expf(sacc[na][h * 2 + 1] - mn);
                sacc[na][h * 2 + 0] = p0;
                sacc[na][h * 2 + 1] = p1;
                sum += p0 + p1;
            }
            sum += __shfl_xor_sync(0xffffffffu, sum, 1);
            sum += __shfl_xor_sync(0xffffffffu, sum, 2);
            lrow[h] = lrow[h] * corr + sum;
#pragma unroll
            for (int na = 0; na < 8; na++) {
                of[na][h * 2 + 0] *= corr;
                of[na][h * 2 + 1] *= corr;
            }
        }

        // ---- O += P V : P a-frags built in registers from sacc ----
#pragma unroll
        for (int ka = 0; ka < 4; ka++) {       // tpair chunks (k16 over t)
            uint32_t pah[4], pal[4];
            split2(sacc[2 * ka][0],     sacc[2 * ka][1],     pah[0], pal[0]);
            split2(sacc[2 * ka][2],     sacc[2 * ka][3],     pah[1], pal[1]);
            split2(sacc[2 * ka + 1][0], sacc[2 * ka + 1][1], pah[2], pal[2]);
            split2(sacc[2 * ka + 1][2], sacc[2 * ka + 1][3], pah[3], pal[3]);
#pragma unroll
            for (int nb = 0; nb < 4; nb++) {   // d block pairs (16 d)
                uint32_t off = ((f_row + nb * 16) * ATS + ka * 8 + f_col) * 4;
                uint32_t vh4[4], vl4[4];
                ldsm4(vh4, st + A_VHI * 4 + off);
                ldsm4(vl4, st + A_VLO * 4 + off);
                mma16(of[2 * nb],     pah, &vh4[0]);
                mma16(of[2 * nb],     pal, &vh4[0]);
                mma16(of[2 * nb],     pah, &vl4[0]);
                mma16(of[2 * nb + 1], pah, &vh4[2]);
                mma16(of[2 * nb + 1], pal, &vh4[2]);
                mma16(of[2 * nb + 1], pah, &vl4[2]);
            }
        }
    }

    // ---- finalize: write O hi/lo bf16 pairs [m][512 kpair] ----
    const int bb = bh >> 4, hh = bh & 15;
    float inv0 = 1.f / lrow[0];
    float inv1 = 1.f / lrow[1];
    int q = qb * 128 + wrow + g;
    size_t r0 = (size_t)(bb * T_ + q) * 512 + hh * 32;
    size_t r8 = r0 + 8 * 512;
#pragma unroll
    for (int na = 0; na < 8; na++) {
        int dp = (na * 8 + tg * 2) >> 1;
        uint32_t h0, l0, h1, l1;
        split2(of[na][0] * inv0, of[na][1] * inv0, h0, l0);
        split2(of[na][2] * inv1, of[na][3] * inv1, h1, l1);
        g_Oh[r0 + dp] = h0;  g_Ol[r0 + dp] = l0;
        g_Oh[r8 + dp] = h1;  g_Ol[r8 + dp] = l1;
    }
}

// ---------------- launch ----------------
extern "C" void kernel_launch(void* const* d_in, const int* in_sizes, int n_in,
                              void* d_out, int out_size)
{
    const float* x    = (const float*)d_in[0];
    const float* Wqkv = (const float*)d_in[1];
    const float* bqkv = (const float*)d_in[2];
    const float* Wout = (const float*)d_in[3];
    const float* bout = (const float*)d_in[4];
    float* out = (float*)d_out;

    static bool attr_done = false;
    if (!attr_done) {
        cudaFuncSetAttribute((void*)gemmb<0>, cudaFuncAttributeMaxDynamicSharedMemorySize, GEMM_SMEM);
        cudaFuncSetAttribute((void*)gemmb<1>, cudaFuncAttributeMaxDynamicSharedMemorySize, GEMM_SMEM);
        cudaFuncSetAttribute((void*)attnb,    cudaFuncAttributeMaxDynamicSharedMemorySize, ATTN_SMEM);
        attr_done = true;
    }

    prep_x<<<4096 * 512 / 256, 256>>>(x);
    prep_w<N1, 0><<<dim3(N1 / 64, 16), 256>>>(Wqkv);
    prep_w<N2, 1><<<dim3(N2 / 64, 16), 256>>>(Wout);

    dim3 g1(N1 / 128, M_ / 128);   // (24, 32)
    gemmb<0><<<g1, 256, GEMM_SMEM>>>(bqkv, nullptr);

    dim3 ga(T_ / 128, B_ * H_);    // (16, 32)
    attnb<<<ga, 256, ATTN_SMEM>>>();

    dim3 g2(N2 / 128, M_ / 128);   // (8, 32)
    gemmb<1><<<g2, 256, GEMM_SMEM>>>(bout, out);
}